// round 1
// baseline (speedup 1.0000x reference)
#include <cuda_runtime.h>
#include <cuda_bf16.h>

#define B_DIM 512
#define P_DIM 512
#define F_DIM 1024
#define EPS_T 1e-8f

#define SPLITK 4
#define KC (F_DIM / SPLITK)   // 256 k-extent per split
#define BM 64
#define BN 64
#define BK 32
#define NT (KC / BK)          // 8 tiles per split

// Scratch (static device globals — no allocation allowed)
__device__ float g_xsT[F_DIM * B_DIM];            // sigmoid(x) transposed [F][B]
__device__ float g_wsT[F_DIM * P_DIM];            // sigmoid(w) transposed [F][P]
__device__ float g_Sx[B_DIM];
__device__ float g_Sw[P_DIM];
__device__ float g_part[SPLITK * B_DIM * P_DIM];  // split-K partial intersections

// ---------------------------------------------------------------------------
// Kernel 1: sigmoid + transpose + row sums.
// One block per row. Rows 0..511 -> x, rows 512..1023 -> w.
// ---------------------------------------------------------------------------
__global__ __launch_bounds__(256) void sig_rowsum_kernel(
    const float* __restrict__ x, const float* __restrict__ w)
{
    int row = blockIdx.x;
    int tid = threadIdx.x;

    const float* src;
    float* dstT;
    float* sumdst;
    int col;
    if (row < B_DIM) {
        src = x + (size_t)row * F_DIM;
        dstT = g_xsT;
        sumdst = g_Sx + row;
        col = row;
    } else {
        int p = row - B_DIM;
        src = w + (size_t)p * F_DIM;
        dstT = g_wsT;
        sumdst = g_Sw + p;
        col = p;
    }

    // 1024 elems / 256 threads = 4 per thread (vectorized read)
    float4 v = *reinterpret_cast<const float4*>(src + tid * 4);
    float s0 = 1.0f / (1.0f + __expf(-v.x));
    float s1 = 1.0f / (1.0f + __expf(-v.y));
    float s2 = 1.0f / (1.0f + __expf(-v.z));
    float s3 = 1.0f / (1.0f + __expf(-v.w));

    int f0 = tid * 4;
    dstT[(size_t)(f0 + 0) * 512 + col] = s0;
    dstT[(size_t)(f0 + 1) * 512 + col] = s1;
    dstT[(size_t)(f0 + 2) * 512 + col] = s2;
    dstT[(size_t)(f0 + 3) * 512 + col] = s3;

    float local = s0 + s1 + s2 + s3;
    // warp reduce
    #pragma unroll
    for (int o = 16; o > 0; o >>= 1)
        local += __shfl_xor_sync(0xFFFFFFFFu, local, o);

    __shared__ float red[8];
    if ((tid & 31) == 0) red[tid >> 5] = local;
    __syncthreads();
    if (tid == 0) {
        float t = 0.f;
        #pragma unroll
        for (int i = 0; i < 8; i++) t += red[i];
        *sumdst = t;
    }
}

// ---------------------------------------------------------------------------
// Kernel 2: pairwise min-sum (the O(B*P*F) part), split-K.
// grid (P/BN, B/BM, SPLITK), 256 threads (16x16), 4x4 register tile.
// ---------------------------------------------------------------------------
__global__ __launch_bounds__(256, 2) void tversky_main_kernel()
{
    __shared__ float xs_s[2][BK][BM];
    __shared__ float ws_s[2][BK][BN];

    int tid = threadIdx.x;
    int tx = tid & 15;          // N direction
    int ty = tid >> 4;          // M direction
    int m0 = blockIdx.y * BM;
    int n0 = blockIdx.x * BN;
    int kbase = blockIdx.z * KC;

    // Loader mapping: float4 index l in [0,512) per matrix per tile:
    //   krow = l >> 4 (0..31), quad = l & 15. This thread handles l=tid (krow 0..15)
    //   and l=tid+256 (krow 16..31). Fully coalesced global reads (transposed layout).
    int krow = tid >> 4;        // 0..15
    int quad = tid & 15;

    const float* xg = g_xsT + m0 + quad * 4;
    const float* wg = g_wsT + n0 + quad * 4;

    float acc[4][4];
    #pragma unroll
    for (int i = 0; i < 4; i++)
        #pragma unroll
        for (int j = 0; j < 4; j++) acc[i][j] = 0.f;

    float4 rx0, rx1, rw0, rw1;

    // prologue: load tile 0
    {
        int kr = kbase + krow;
        rx0 = *reinterpret_cast<const float4*>(xg + (size_t)kr * 512);
        rx1 = *reinterpret_cast<const float4*>(xg + (size_t)(kr + 16) * 512);
        rw0 = *reinterpret_cast<const float4*>(wg + (size_t)kr * 512);
        rw1 = *reinterpret_cast<const float4*>(wg + (size_t)(kr + 16) * 512);
        *reinterpret_cast<float4*>(&xs_s[0][krow][quad * 4]) = rx0;
        *reinterpret_cast<float4*>(&xs_s[0][krow + 16][quad * 4]) = rx1;
        *reinterpret_cast<float4*>(&ws_s[0][krow][quad * 4]) = rw0;
        *reinterpret_cast<float4*>(&ws_s[0][krow + 16][quad * 4]) = rw1;
    }
    __syncthreads();

    for (int t = 0; t < NT; t++) {
        int buf = t & 1;
        if (t + 1 < NT) {
            int kr = kbase + (t + 1) * BK + krow;
            rx0 = *reinterpret_cast<const float4*>(xg + (size_t)kr * 512);
            rx1 = *reinterpret_cast<const float4*>(xg + (size_t)(kr + 16) * 512);
            rw0 = *reinterpret_cast<const float4*>(wg + (size_t)kr * 512);
            rw1 = *reinterpret_cast<const float4*>(wg + (size_t)(kr + 16) * 512);
        }

        #pragma unroll 16
        for (int kk = 0; kk < BK; kk++) {
            float4 xv = *reinterpret_cast<const float4*>(&xs_s[buf][kk][ty * 4]);
            float4 wv = *reinterpret_cast<const float4*>(&ws_s[buf][kk][tx * 4]);
            float xa[4] = {xv.x, xv.y, xv.z, xv.w};
            float wa[4] = {wv.x, wv.y, wv.z, wv.w};
            #pragma unroll
            for (int i = 0; i < 4; i++)
                #pragma unroll
                for (int j = 0; j < 4; j++)
                    acc[i][j] += fminf(xa[i], wa[j]);
        }

        if (t + 1 < NT) {
            int nb = (t + 1) & 1;
            *reinterpret_cast<float4*>(&xs_s[nb][krow][quad * 4]) = rx0;
            *reinterpret_cast<float4*>(&xs_s[nb][krow + 16][quad * 4]) = rx1;
            *reinterpret_cast<float4*>(&ws_s[nb][krow][quad * 4]) = rw0;
            *reinterpret_cast<float4*>(&ws_s[nb][krow + 16][quad * 4]) = rw1;
            __syncthreads();
        }
    }

    // write split-K partials
    float* base = g_part + (size_t)blockIdx.z * B_DIM * P_DIM;
    #pragma unroll
    for (int i = 0; i < 4; i++) {
        float4 v = make_float4(acc[i][0], acc[i][1], acc[i][2], acc[i][3]);
        *reinterpret_cast<float4*>(&base[(size_t)(m0 + ty * 4 + i) * P_DIM + n0 + tx * 4]) = v;
    }
}

// ---------------------------------------------------------------------------
// Kernel 3: combine partials + Tversky epilogue.
//   x_diff = Sx - I, w_diff = Sw - I
//   out = I / (I + alpha*(Sx-I) + beta*(Sw-I) + eps) + bias
// ---------------------------------------------------------------------------
__global__ __launch_bounds__(256) void finalize_kernel(
    const float* __restrict__ bias,
    const float* __restrict__ alpha,
    const float* __restrict__ beta,
    float* __restrict__ out)
{
    int idx = blockIdx.x * 256 + threadIdx.x;      // 0 .. 262143
    int m = idx >> 9;
    int n = idx & 511;

    const int STRIDE = B_DIM * P_DIM;
    float I = g_part[idx] + g_part[idx + STRIDE]
            + g_part[idx + 2 * STRIDE] + g_part[idx + 3 * STRIDE];

    float a = *alpha;
    float b = *beta;
    float denom = I + a * (g_Sx[m] - I) + b * (g_Sw[n] - I) + EPS_T;
    out[idx] = I / denom + bias[n];
}

// ---------------------------------------------------------------------------
extern "C" void kernel_launch(void* const* d_in, const int* in_sizes, int n_in,
                              void* d_out, int out_size)
{
    const float* x      = (const float*)d_in[0];   // (512, 1024)
    const float* weight = (const float*)d_in[1];   // (512, 1024)
    const float* bias   = (const float*)d_in[2];   // (512,)
    const float* alpha  = (const float*)d_in[3];   // scalar
    const float* beta   = (const float*)d_in[4];   // scalar
    float* out = (float*)d_out;                    // (512, 512)

    sig_rowsum_kernel<<<B_DIM + P_DIM, 256>>>(x, weight);
    tversky_main_kernel<<<dim3(P_DIM / BN, B_DIM / BM, SPLITK), 256>>>();
    finalize_kernel<<<(B_DIM * P_DIM) / 256, 256>>>(bias, alpha, beta, out);
}

// round 3
// speedup vs baseline: 1.1288x; 1.1288x over previous
#include <cuda_runtime.h>
#include <cuda_bf16.h>

#define B_DIM 512
#define P_DIM 512
#define F_DIM 1024
#define EPS_T 1e-8f

#define SPLITK 8
#define KC (F_DIM / SPLITK)   // 128 k-extent per split
#define BM 64
#define BN 64
#define BK 32
#define NT (KC / BK)          // 4 tiles per split

// Scratch (static device globals — no allocation allowed)
__device__ float g_xsT[F_DIM * B_DIM];            // sigmoid(x) transposed [F][B]
__device__ float g_wsT[F_DIM * P_DIM];            // sigmoid(w) transposed [F][P]
__device__ float g_Spart[8][B_DIM + P_DIM];       // per-fchunk partial row sums
__device__ float g_part[SPLITK * B_DIM * P_DIM];  // split-K partial intersections

// ---------------------------------------------------------------------------
// Kernel 1: sigmoid + COALESCED transpose (smem-tiled) + partial row sums.
// grid (8 fchunks of 128, 32 rowgroups of 32). rows 0..511 -> x, 512..1023 -> w.
// ---------------------------------------------------------------------------
__global__ __launch_bounds__(256) void prep_kernel(
    const float* __restrict__ x, const float* __restrict__ w)
{
    __shared__ float tile[32][33];

    int tid = threadIdx.x;
    int row0 = blockIdx.y * 32;       // combined row index base
    int f0 = blockIdx.x * 128;

    bool isX = (row0 < B_DIM);
    const float* src = isX ? (x + (size_t)row0 * F_DIM)
                           : (w + (size_t)(row0 - B_DIM) * F_DIM);
    float* dstT = isX ? g_xsT : g_wsT;
    int col0 = isX ? row0 : (row0 - B_DIM);

    int r  = tid >> 3;                // 0..31 source row within group
    int c4 = (tid & 7) * 4;           // 0..28 f offset (float4)
    int fr = tid >> 3;                // 0..31 f row for transposed store
    int cq = tid & 7;                 // 0..7 col quad for transposed store

    float rsum = 0.f;

    #pragma unroll
    for (int sub = 0; sub < 4; sub++) {
        int fbase = f0 + sub * 32;
        float4 v = *reinterpret_cast<const float4*>(src + (size_t)r * F_DIM + fbase + c4);
        float s0 = 1.0f / (1.0f + __expf(-v.x));
        float s1 = 1.0f / (1.0f + __expf(-v.y));
        float s2 = 1.0f / (1.0f + __expf(-v.z));
        float s3 = 1.0f / (1.0f + __expf(-v.w));
        rsum += (s0 + s1) + (s2 + s3);

        tile[r][c4 + 0] = s0;
        tile[r][c4 + 1] = s1;
        tile[r][c4 + 2] = s2;
        tile[r][c4 + 3] = s3;
        __syncthreads();

        // transposed, coalesced store: dstT[f][col0 .. col0+31]
        float4 o = make_float4(tile[cq * 4 + 0][fr], tile[cq * 4 + 1][fr],
                               tile[cq * 4 + 2][fr], tile[cq * 4 + 3][fr]);
        *reinterpret_cast<float4*>(dstT + (size_t)(fbase + fr) * 512 + col0 + cq * 4) = o;
        __syncthreads();
    }

    // reduce rsum across the 8 threads sharing source row r (lanes q=0..7)
    rsum += __shfl_xor_sync(0xFFFFFFFFu, rsum, 1);
    rsum += __shfl_xor_sync(0xFFFFFFFFu, rsum, 2);
    rsum += __shfl_xor_sync(0xFFFFFFFFu, rsum, 4);
    if ((tid & 7) == 0)
        g_Spart[blockIdx.x][row0 + r] = rsum;
}

// ---------------------------------------------------------------------------
// Kernel 2: pairwise min-sum (the O(B*P*F) part), split-K=8.
// grid (P/BN, B/BM, SPLITK) = (8, 8, 8) = 512 blocks, 256 threads, 4x4/thread.
// ---------------------------------------------------------------------------
__global__ __launch_bounds__(256, 3) void tversky_main_kernel()
{
    __shared__ float xs_s[2][BK][BM];
    __shared__ float ws_s[2][BK][BN];

    int tid = threadIdx.x;
    int tx = tid & 15;          // N direction
    int ty = tid >> 4;          // M direction
    int m0 = blockIdx.y * BM;
    int n0 = blockIdx.x * BN;
    int kbase = blockIdx.z * KC;

    int krow = tid >> 4;        // 0..15
    int quad = tid & 15;

    const float* xg = g_xsT + m0 + quad * 4;
    const float* wg = g_wsT + n0 + quad * 4;

    float acc[4][4];
    #pragma unroll
    for (int i = 0; i < 4; i++)
        #pragma unroll
        for (int j = 0; j < 4; j++) acc[i][j] = 0.f;

    float4 rx0, rx1, rw0, rw1;

    // prologue: load tile 0
    {
        int kr = kbase + krow;
        rx0 = *reinterpret_cast<const float4*>(xg + (size_t)kr * 512);
        rx1 = *reinterpret_cast<const float4*>(xg + (size_t)(kr + 16) * 512);
        rw0 = *reinterpret_cast<const float4*>(wg + (size_t)kr * 512);
        rw1 = *reinterpret_cast<const float4*>(wg + (size_t)(kr + 16) * 512);
        *reinterpret_cast<float4*>(&xs_s[0][krow][quad * 4]) = rx0;
        *reinterpret_cast<float4*>(&xs_s[0][krow + 16][quad * 4]) = rx1;
        *reinterpret_cast<float4*>(&ws_s[0][krow][quad * 4]) = rw0;
        *reinterpret_cast<float4*>(&ws_s[0][krow + 16][quad * 4]) = rw1;
    }
    __syncthreads();

    for (int t = 0; t < NT; t++) {
        int buf = t & 1;
        if (t + 1 < NT) {
            int kr = kbase + (t + 1) * BK + krow;
            rx0 = *reinterpret_cast<const float4*>(xg + (size_t)kr * 512);
            rx1 = *reinterpret_cast<const float4*>(xg + (size_t)(kr + 16) * 512);
            rw0 = *reinterpret_cast<const float4*>(wg + (size_t)kr * 512);
            rw1 = *reinterpret_cast<const float4*>(wg + (size_t)(kr + 16) * 512);
        }

        #pragma unroll 8
        for (int kk = 0; kk < BK; kk++) {
            float4 xv = *reinterpret_cast<const float4*>(&xs_s[buf][kk][ty * 4]);
            float4 wv = *reinterpret_cast<const float4*>(&ws_s[buf][kk][tx * 4]);
            float xa[4] = {xv.x, xv.y, xv.z, xv.w};
            float wa[4] = {wv.x, wv.y, wv.z, wv.w};
            #pragma unroll
            for (int i = 0; i < 4; i++)
                #pragma unroll
                for (int j = 0; j < 4; j++)
                    acc[i][j] += fminf(xa[i], wa[j]);
        }

        if (t + 1 < NT) {
            int nb = (t + 1) & 1;
            *reinterpret_cast<float4*>(&xs_s[nb][krow][quad * 4]) = rx0;
            *reinterpret_cast<float4*>(&xs_s[nb][krow + 16][quad * 4]) = rx1;
            *reinterpret_cast<float4*>(&ws_s[nb][krow][quad * 4]) = rw0;
            *reinterpret_cast<float4*>(&ws_s[nb][krow + 16][quad * 4]) = rw1;
            __syncthreads();
        }
    }

    // write split-K partials (L2-resident; read back by finalize)
    float* base = g_part + (size_t)blockIdx.z * (B_DIM * P_DIM);
    #pragma unroll
    for (int i = 0; i < 4; i++) {
        float4 v = make_float4(acc[i][0], acc[i][1], acc[i][2], acc[i][3]);
        *reinterpret_cast<float4*>(&base[(size_t)(m0 + ty * 4 + i) * P_DIM + n0 + tx * 4]) = v;
    }
}

// ---------------------------------------------------------------------------
// Kernel 3: collapse Spart -> Sx/Sw, combine split-K partials, Tversky epilogue.
//   out = I / (I + alpha*(Sx-I) + beta*(Sw-I) + eps) + bias
// Each block covers 256 consecutive idx -> single m per block (512 % 256 == 0).
// ---------------------------------------------------------------------------
__global__ __launch_bounds__(256) void finalize_kernel(
    const float* __restrict__ bias,
    const float* __restrict__ alpha,
    const float* __restrict__ beta,
    float* __restrict__ out)
{
    __shared__ float sSx;
    int idx = blockIdx.x * 256 + threadIdx.x;      // 0 .. 262143
    int m = idx >> 9;
    int n = idx & 511;

    if (threadIdx.x == 0) {
        float t = 0.f;
        #pragma unroll
        for (int c = 0; c < 8; c++) t += g_Spart[c][m];
        sSx = t;
    }

    float Sw = 0.f;
    #pragma unroll
    for (int c = 0; c < 8; c++) Sw += g_Spart[c][B_DIM + n];

    const int STRIDE = B_DIM * P_DIM;
    float I = 0.f;
    #pragma unroll
    for (int s = 0; s < SPLITK; s++) I += g_part[idx + s * STRIDE];

    __syncthreads();
    float Sx = sSx;

    float a = *alpha;
    float b = *beta;
    float denom = I + a * (Sx - I) + b * (Sw - I) + EPS_T;
    out[idx] = I / denom + bias[n];
}

// ---------------------------------------------------------------------------
extern "C" void kernel_launch(void* const* d_in, const int* in_sizes, int n_in,
                              void* d_out, int out_size)
{
    const float* x      = (const float*)d_in[0];   // (512, 1024)
    const float* weight = (const float*)d_in[1];   // (512, 1024)
    const float* bias   = (const float*)d_in[2];   // (512,)
    const float* alpha  = (const float*)d_in[3];   // scalar
    const float* beta   = (const float*)d_in[4];   // scalar
    float* out = (float*)d_out;                    // (512, 512)

    prep_kernel<<<dim3(8, 32), 256>>>(x, weight);
    tversky_main_kernel<<<dim3(P_DIM / BN, B_DIM / BM, SPLITK), 256>>>();
    finalize_kernel<<<(B_DIM * P_DIM) / 256, 256>>>(bias, alpha, beta, out);
}